// round 15
// baseline (speedup 1.0000x reference)
#include <cuda_runtime.h>
#include <cuda_fp16.h>
#include <stdint.h>

#define NN 8192
#define DH 64
#define KC 64              // j's per chunk
#define KSPLIT 2
#define KHALF (NN / KSPLIT)
#define NCH (KHALF / KC)   // 64 chunks
#define TPB 256
#define TILE_I 64
// smem: W tile 64x64 fp16 (8KB) x2, B tile 64x64 fp16 (8KB) x2
#define WOFF0 0
#define WOFF1 8192
#define BOFF0 16384
#define BOFF1 24576
#define SMEM_BYTES 32768
#define RED_STRIDE 68      // fp32 reduction buffer stride (bank-safe, float2-aligned)

// ---------------- device scratch ----------------
__device__ unsigned short g_adjp[NN * 512];    // packed adjacency bits (8MB)
__device__ unsigned short g_WhT[DH * NN];      // Wh^T fp16 [64][8192]
__device__ uint2 g_iAC[NN];                    // {half2(exp(src)), half2(exp(.2src))}
__device__ unsigned short g_jB[NN];            // half exp(dst)
__device__ unsigned short g_jD[NN];            // half exp(.2 dst)
__device__ float g_part[KSPLIT * NN * DH];     // K-split partial numerators
__device__ float g_den[KSPLIT * NN];           // K-split partial denominators

// ---------------- helpers ----------------
__device__ __forceinline__ uint32_t smem_u32(const void* p) {
    uint32_t a;
    asm("{ .reg .u64 t; cvta.to.shared.u64 t, %1; cvt.u32.u64 %0, t; }" : "=r"(a) : "l"(p));
    return a;
}
#define SWZ(off) ((off) ^ (((off) >> 3) & 0x70))

#define CPA16(d, s) asm volatile("cp.async.cg.shared.global [%0], [%1], 16;" :: "r"(d), "l"(s))
#define CPA_COMMIT() asm volatile("cp.async.commit_group;" ::: "memory")
#define CPA_WAIT0()  asm volatile("cp.async.wait_group 0;" ::: "memory")

__device__ __forceinline__ void ldsm_x4(uint32_t& r0, uint32_t& r1, uint32_t& r2, uint32_t& r3,
                                        uint32_t a) {
    asm volatile("ldmatrix.sync.aligned.m8n8.x4.shared.b16 {%0,%1,%2,%3}, [%4];"
                 : "=r"(r0), "=r"(r1), "=r"(r2), "=r"(r3) : "r"(a));
}
__device__ __forceinline__ void mma16816(float* d, const uint32_t* a, const uint32_t* b) {
    asm volatile("mma.sync.aligned.m16n8k16.row.col.f32.f16.f16.f32 "
                 "{%0,%1,%2,%3}, {%4,%5,%6,%7}, {%8,%9}, {%0,%1,%2,%3};"
                 : "+f"(d[0]), "+f"(d[1]), "+f"(d[2]), "+f"(d[3])
                 : "r"(a[0]), "r"(a[1]), "r"(a[2]), "r"(a[3]), "r"(b[0]), "r"(b[1]));
}

// ---------------- prep: x in smem (broadcast), W row in regs ----------------
__global__ void __launch_bounds__(256) prep_kernel(const float* __restrict__ xa,
                                                   const float* __restrict__ xb,
                                                   const float* __restrict__ Wm,
                                                   const float* __restrict__ bv,
                                                   const float* __restrict__ av, int use_gx) {
    __shared__ float xs[64][64];
    __shared__ float whs[64][65];
    __shared__ float as_[2 * DH];
    __shared__ float bsh[DH];
    __shared__ float inv_s[64];
    int t = threadIdx.x;
    int row0 = blockIdx.x * 64;

    if (t < 2 * DH) as_[t] = av[t];
    if (t < DH) bsh[t] = bv[t];
    if (use_gx && t < 64) {
        int row = row0 + t;
        inv_s[t] = 1.0f / (g_den[row] + g_den[NN + row]);
    }
    __syncthreads();

    {
        int r = t >> 2, q = t & 3;
        int row = row0 + r;
        if (use_gx) {
            const float4* p0 = (const float4*)(g_part + (size_t)row * DH) + q * 4;
            const float4* p1 = (const float4*)(g_part + (size_t)(NN + row) * DH) + q * 4;
            float inv = inv_s[r];
#pragma unroll
            for (int k = 0; k < 4; k++) {
                float4 v0 = p0[k], v1 = p1[k];
                xs[r][q * 16 + 4 * k + 0] = fmaxf((v0.x + v1.x) * inv, 0.f);
                xs[r][q * 16 + 4 * k + 1] = fmaxf((v0.y + v1.y) * inv, 0.f);
                xs[r][q * 16 + 4 * k + 2] = fmaxf((v0.z + v1.z) * inv, 0.f);
                xs[r][q * 16 + 4 * k + 3] = fmaxf((v0.w + v1.w) * inv, 0.f);
            }
        } else {
            const float* xr = row < NN / 2 ? xa + (size_t)row * DH
                                           : xb + (size_t)(row - NN / 2) * DH;
#pragma unroll
            for (int k = 0; k < 4; k++) {
                float4 v = ((const float4*)xr)[q * 4 + k];
                xs[r][q * 16 + 4 * k + 0] = v.x;
                xs[r][q * 16 + 4 * k + 1] = v.y;
                xs[r][q * 16 + 4 * k + 2] = v.z;
                xs[r][q * 16 + 4 * k + 3] = v.w;
            }
        }
    }

    int i = t & 63, g = t >> 6;
    float Wr[64];
#pragma unroll
    for (int k = 0; k < 16; k++) {
        float4 w = ((const float4*)(Wm + (size_t)i * DH))[k];
        Wr[4 * k] = w.x; Wr[4 * k + 1] = w.y; Wr[4 * k + 2] = w.z; Wr[4 * k + 3] = w.w;
    }
    __syncthreads();

    float bias = bsh[i];
    int rbase = g * 16;
#pragma unroll
    for (int r = 0; r < 16; r++) {
        int rr = rbase + r;
        float a0 = 0.f, a1 = 0.f, a2 = 0.f, a3 = 0.f;
#pragma unroll
        for (int k = 0; k < 16; k++) {
            float4 xv = *(const float4*)&xs[rr][4 * k];
            a0 = fmaf(Wr[4 * k + 0], xv.x, a0);
            a1 = fmaf(Wr[4 * k + 1], xv.y, a1);
            a2 = fmaf(Wr[4 * k + 2], xv.z, a2);
            a3 = fmaf(Wr[4 * k + 3], xv.w, a3);
        }
        whs[rr][i] = bias + ((a0 + a1) + (a2 + a3));
    }
    __syncthreads();

    {
        int ii = t >> 2, rq = t & 3;
        uint32_t packed[8];
#pragma unroll
        for (int k = 0; k < 8; k++) {
            __half2 h = __floats2half2_rn(whs[rq * 16 + 2 * k][ii], whs[rq * 16 + 2 * k + 1][ii]);
            packed[k] = *(uint32_t*)&h;
        }
        uint4* dst = (uint4*)(g_WhT + (size_t)ii * NN + row0 + rq * 16);
        dst[0] = make_uint4(packed[0], packed[1], packed[2], packed[3]);
        dst[1] = make_uint4(packed[4], packed[5], packed[6], packed[7]);
    }

    {
        int r = t >> 2, q = t & 3;
        float sv = 0.f, dv = 0.f;
#pragma unroll
        for (int k = 0; k < 16; k++) {
            int ii = q * 16 + k;
            float wh = whs[r][ii];
            sv = fmaf(wh, as_[ii], sv);
            dv = fmaf(wh, as_[DH + ii], dv);
        }
        sv += __shfl_xor_sync(0xffffffffu, sv, 1);
        sv += __shfl_xor_sync(0xffffffffu, sv, 2);
        dv += __shfl_xor_sync(0xffffffffu, dv, 1);
        dv += __shfl_xor_sync(0xffffffffu, dv, 2);
        if (q == 0) {
            int row = row0 + r;
            __half2 Ah = __float2half2_rn(expf(sv));
            __half2 Ch = __float2half2_rn(expf(0.2f * sv));
            g_iAC[row] = make_uint2(*(uint32_t*)&Ah, *(uint32_t*)&Ch);
            g_jB[row] = __half_as_ushort(__float2half_rn(expf(dv)));
            g_jD[row] = __half_as_ushort(__float2half_rn(expf(0.2f * dv)));
        }
    }
}

// ---------------- weight-tile generation (half2) + fp32 row-sum ----------------
template<int L0>
__device__ __forceinline__ void gen_store(char* smemp, uint32_t wo, uint32_t wdst0, uint32_t wdst1,
                                          uint32_t A2, uint32_t C2,
                                          const uint4& B0, const uint4& B1,
                                          const uint4& D0, const uint4& D1,
                                          uint32_t bits_in, const int* vi,
                                          unsigned short* packdst, float& dsum) {
    uint32_t Bw[8] = {B0.x, B0.y, B0.z, B0.w, B1.x, B1.y, B1.z, B1.w};
    uint32_t Dw[8] = {D0.x, D0.y, D0.z, D0.w, D1.x, D1.y, D1.z, D1.w};
    uint32_t wv[8];
    uint32_t packbits = 0;
    __half2 A2h = *(__half2*)&A2, C2h = *(__half2*)&C2;
#pragma unroll
    for (int p = 0; p < 8; p++) {
        __half2 ab = __hmul2(A2h, *(__half2*)&Bw[p]);
        __half2 cd = __hmul2(C2h, *(__half2*)&Dw[p]);
        __half2 w = __hmax2(ab, cd);      // exp(leaky_relu(src+dst)) — exp is monotone
        uint32_t m;
        if (L0) {
            int v0 = vi[2 * p], v1 = vi[2 * p + 1];
            m = (v0 != 0 ? 0x0000FFFFu : 0u) | (v1 != 0 ? 0xFFFF0000u : 0u);
            packbits |= (v0 != 0 ? 1u : 0u) << (2 * p);
            packbits |= (v1 != 0 ? 1u : 0u) << (2 * p + 1);
        } else {
            uint32_t e = (bits_in >> (2 * p)) & 3u;
            uint32_t xm = (e * 0x8001u) & 0x10001u;
            m = xm * 0xFFFFu;
        }
        wv[p] = (*(uint32_t*)&w) & m;
    }
    __half2 s01 = __hadd2(*(__half2*)&wv[0], *(__half2*)&wv[1]);
    __half2 s23 = __hadd2(*(__half2*)&wv[2], *(__half2*)&wv[3]);
    __half2 s45 = __hadd2(*(__half2*)&wv[4], *(__half2*)&wv[5]);
    __half2 s67 = __hadd2(*(__half2*)&wv[6], *(__half2*)&wv[7]);
    float2 f0 = __half22float2(__hadd2(s01, s23));
    float2 f1 = __half22float2(__hadd2(s45, s67));
    dsum += (f0.x + f0.y) + (f1.x + f1.y);

    *(uint4*)(smemp + wo + wdst0) = make_uint4(wv[0], wv[1], wv[2], wv[3]);
    *(uint4*)(smemp + wo + wdst1) = make_uint4(wv[4], wv[5], wv[6], wv[7]);
    if (L0) *packdst = (unsigned short)packbits;
}

// ---------------- attn: HMMA flash-GAT, 64x4096 per CTA ----------------
// GEMM warp mapping: wm = M-tile (4x16 rows), kh = k-half (0/1). Each warp
// computes 16 rows x full 64 N over k in [kh*32, kh*32+32). A dup x1, B dup x4
// over half-k -> 80 ldsm_x4/chunk (vs 96). k-half accumulators combined once
// in the epilogue via smem.
template<int L0>
__global__ void __launch_bounds__(TPB, 3) attn_mma(const int* __restrict__ adj) {
    extern __shared__ char smem[];
    uint32_t sb = smem_u32(smem);
    int t = threadIdx.x, wid = t >> 5, lane = t & 31;
    int tile = blockIdx.x >> 1, ks = blockIdx.x & 1;
    int i0 = tile * TILE_I, jbase = ks * KHALF;

    // ---- gen mapping: thread -> row i_loc, 16 j's at quarter jq16 ----
    int i_loc = t >> 2, jq16 = t & 3;
    int irow = i0 + i_loc;
    uint2 ac = g_iAC[irow];
    uint32_t wdst0 = SWZ((uint32_t)(i_loc * 128 + jq16 * 32));
    uint32_t wdst1 = SWZ((uint32_t)(i_loc * 128 + jq16 * 32 + 16));
    const uint4* pB = (const uint4*)(g_jB + jbase) + jq16 * 2;
    const uint4* pD = (const uint4*)(g_jD + jbase) + jq16 * 2;
    const int4* pAdj = (const int4*)(adj + (size_t)irow * NN + jbase) + jq16 * 4;
    unsigned short* pPack = g_adjp + (size_t)irow * 512 + (jbase >> 4) + jq16;
    float dsum = 0.f;

    // ---- B staging (cp.async): 512 16B segs = 2/thread ----
    int s0 = t, s1 = t + 256;
    uint32_t bd0 = SWZ((uint32_t)((s0 >> 3) * 128 + (s0 & 7) * 16));
    uint32_t bd1 = SWZ((uint32_t)((s1 >> 3) * 128 + (s1 & 7) * 16));
    const unsigned short* bs0p = g_WhT + (size_t)(s0 >> 3) * NN + jbase + (s0 & 7) * 8;
    const unsigned short* bs1p = g_WhT + (size_t)(s1 >> 3) * NN + jbase + (s1 & 7) * 8;

    // ---- GEMM mapping: 8 warps = 4 M-tiles(16) x 2 k-halves(32) ----
    int wm = wid & 3, kh = wid >> 2;
    int lr = lane & 7, lsel = lane >> 3;
    float acc[8][4];
#pragma unroll
    for (int n = 0; n < 8; n++)
#pragma unroll
        for (int p = 0; p < 4; p++) acc[n][p] = 0.f;

    // ---- prefetch regs for chunk 0 ----
    uint4 Bq0 = pB[0], Bq1 = pB[1], Dq0 = pD[0], Dq1 = pD[1];
    uint32_t bits = 0;
    int4 rv[4];
    if (L0) {
        rv[0] = __ldcs(pAdj + 0); rv[1] = __ldcs(pAdj + 1);
        rv[2] = __ldcs(pAdj + 2); rv[3] = __ldcs(pAdj + 3);
    } else bits = pPack[0];

    // ---- stage chunk 0 ----
    CPA16(sb + BOFF0 + bd0, bs0p);
    CPA16(sb + BOFF0 + bd1, bs1p);
    CPA_COMMIT();
    gen_store<L0>(smem, WOFF0, wdst0, wdst1, ac.x, ac.y, Bq0, Bq1, Dq0, Dq1,
                  bits, (const int*)rv, pPack, dsum);
    Bq0 = pB[8]; Bq1 = pB[9]; Dq0 = pD[8]; Dq1 = pD[9];
    if (L0) {
        rv[0] = __ldcs(pAdj + 16); rv[1] = __ldcs(pAdj + 17);
        rv[2] = __ldcs(pAdj + 18); rv[3] = __ldcs(pAdj + 19);
    } else bits = pPack[4];
    CPA_WAIT0();
    __syncthreads();

    for (int c = 0; c < NCH; c++) {
        int buf = c & 1;
        if (c + 1 < NCH) {
            int nb = buf ^ 1;
            uint32_t bo = nb ? BOFF1 : BOFF0, wo = nb ? WOFF1 : WOFF0;
            CPA16(sb + bo + bd0, bs0p + (c + 1) * 64);
            CPA16(sb + bo + bd1, bs1p + (c + 1) * 64);
            CPA_COMMIT();
            gen_store<L0>(smem, wo, wdst0, wdst1, ac.x, ac.y, Bq0, Bq1, Dq0, Dq1,
                          bits, (const int*)rv, pPack + (c + 1) * 4, dsum);
            if (c + 2 < NCH) {
                Bq0 = pB[(c + 2) * 8]; Bq1 = pB[(c + 2) * 8 + 1];
                Dq0 = pD[(c + 2) * 8]; Dq1 = pD[(c + 2) * 8 + 1];
                if (L0) {
                    rv[0] = __ldcs(pAdj + (c + 2) * 16);     rv[1] = __ldcs(pAdj + (c + 2) * 16 + 1);
                    rv[2] = __ldcs(pAdj + (c + 2) * 16 + 2); rv[3] = __ldcs(pAdj + (c + 2) * 16 + 3);
                } else bits = pPack[(c + 2) * 4];
            }
        }

        // ---- GEMM on chunk c: this warp's k range = kh*32 .. kh*32+31 ----
        uint32_t wbase = sb + (buf ? WOFF1 : WOFF0);
        uint32_t bbase = sb + (buf ? BOFF1 : BOFF0);
#pragma unroll
        for (int kq = 0; kq < 2; kq++) {
            int k0 = kh * 32 + kq * 16;
            uint32_t af[4], bf[16];
            uint32_t a_adr = wbase + SWZ((uint32_t)((wm * 16 + lr + (lsel & 1) * 8) * 128 + ((lsel >> 1) * 8 + k0) * 2));
            ldsm_x4(af[0], af[1], af[2], af[3], a_adr);
#pragma unroll
            for (int p = 0; p < 4; p++) {
                uint32_t b_adr = bbase + SWZ((uint32_t)((p * 16 + lr + (lsel >> 1) * 8) * 128 + ((lsel & 1) * 8 + k0) * 2));
                ldsm_x4(bf[p * 4 + 0], bf[p * 4 + 1], bf[p * 4 + 2], bf[p * 4 + 3], b_adr);
            }
#pragma unroll
            for (int p = 0; p < 4; p++) {
                mma16816(acc[p * 2 + 0], af, bf + p * 4 + 0);
                mma16816(acc[p * 2 + 1], af, bf + p * 4 + 2);
            }
        }
        CPA_WAIT0();
        __syncthreads();
    }

    // ---- denominator: reduce over the 4 gen threads of each row ----
    dsum += __shfl_xor_sync(0xffffffffu, dsum, 1);
    dsum += __shfl_xor_sync(0xffffffffu, dsum, 2);
    if (jq16 == 0) g_den[(size_t)ks * NN + irow] = dsum;

    // ---- epilogue: combine k-halves via smem, write partial numerators ----
    float* red = (float*)smem;   // 64 x RED_STRIDE fp32 = 17408 B (reuses tile buffers)
    int erow = wm * 16 + (lane >> 2);
    int ecol = (lane & 3) * 2;
    if (kh == 1) {
#pragma unroll
        for (int nt = 0; nt < 8; nt++) {
            *(float2*)&red[(size_t)erow * RED_STRIDE + nt * 8 + ecol] =
                make_float2(acc[nt][0], acc[nt][1]);
            *(float2*)&red[(size_t)(erow + 8) * RED_STRIDE + nt * 8 + ecol] =
                make_float2(acc[nt][2], acc[nt][3]);
        }
    }
    __syncthreads();
    if (kh == 0) {
        float* base = g_part + (size_t)ks * NN * DH;
        int row0 = i0 + erow;
#pragma unroll
        for (int nt = 0; nt < 8; nt++) {
            float2 r0 = *(float2*)&red[(size_t)erow * RED_STRIDE + nt * 8 + ecol];
            float2 r1 = *(float2*)&red[(size_t)(erow + 8) * RED_STRIDE + nt * 8 + ecol];
            int col = nt * 8 + ecol;
            *(float2*)(base + (size_t)row0 * DH + col) =
                make_float2(acc[nt][0] + r0.x, acc[nt][1] + r0.y);
            *(float2*)(base + (size_t)(row0 + 8) * DH + col) =
                make_float2(acc[nt][2] + r1.x, acc[nt][3] + r1.y);
        }
    }
}

// ---------------- final: fused combine + out = x @ out_w^T + out_b ----------------
__global__ void __launch_bounds__(256) final_kernel(const float* __restrict__ Wm,
                                                    const float* __restrict__ bv,
                                                    float* __restrict__ out) {
    __shared__ float xs[64][64];
    __shared__ float bsh[DH];
    __shared__ float inv_s[64];
    int t = threadIdx.x;
    int row0 = blockIdx.x * 64;
    if (t < DH) bsh[t] = bv[t];
    if (t < 64) {
        int row = row0 + t;
        inv_s[t] = 1.0f / (g_den[row] + g_den[NN + row]);
    }
    __syncthreads();

    {
        int r = t >> 2, q = t & 3;
        int row = row0 + r;
        const float4* p0 = (const float4*)(g_part + (size_t)row * DH) + q * 4;
        const float4* p1 = (const float4*)(g_part + (size_t)(NN + row) * DH) + q * 4;
        float inv = inv_s[r];
#pragma unroll
        for (int k = 0; k < 4; k++) {
            float4 v0 = p0[k], v1 = p1[k];
            xs[r][q * 16 + 4 * k + 0] = fmaxf((v0.x + v1.x) * inv, 0.f);
            xs[r][q * 16 + 4 * k + 1] = fmaxf((v0.y + v1.y) * inv, 0.f);
            xs[r][q * 16 + 4 * k + 2] = fmaxf((v0.z + v1.z) * inv, 0.f);
            xs[r][q * 16 + 4 * k + 3] = fmaxf((v0.w + v1.w) * inv, 0.f);
        }
    }

    int i = t & 63, g = t >> 6;
    float Wr[64];
#pragma unroll
    for (int k = 0; k < 16; k++) {
        float4 w = ((const float4*)(Wm + (size_t)i * DH))[k];
        Wr[4 * k] = w.x; Wr[4 * k + 1] = w.y; Wr[4 * k + 2] = w.z; Wr[4 * k + 3] = w.w;
    }
    __syncthreads();

    float bias = bsh[i];
    int rbase = g * 16;
#pragma unroll
    for (int r = 0; r < 16; r++) {
        int rr = rbase + r;
        float a0 = 0.f, a1 = 0.f, a2 = 0.f, a3 = 0.f;
#pragma unroll
        for (int k = 0; k < 16; k++) {
            float4 xv = *(const float4*)&xs[rr][4 * k];
            a0 = fmaf(Wr[4 * k + 0], xv.x, a0);
            a1 = fmaf(Wr[4 * k + 1], xv.y, a1);
            a2 = fmaf(Wr[4 * k + 2], xv.z, a2);
            a3 = fmaf(Wr[4 * k + 3], xv.w, a3);
        }
        out[(size_t)(row0 + rr) * DH + i] = bias + ((a0 + a1) + (a2 + a3));
    }
}

// ---------------- launch ----------------
extern "C" void kernel_launch(void* const* d_in, const int* in_sizes, int n_in,
                              void* d_out, int out_size) {
    const int*   adj  = (const int*)d_in[0];
    const float* user = (const float*)d_in[1];
    const float* item = (const float*)d_in[2];
    const float* W0   = (const float*)d_in[3];
    const float* b0   = (const float*)d_in[4];
    const float* a0   = (const float*)d_in[5];
    const float* W1   = (const float*)d_in[6];
    const float* b1   = (const float*)d_in[7];
    const float* a1   = (const float*)d_in[8];
    const float* ow   = (const float*)d_in[9];
    const float* ob   = (const float*)d_in[10];

    cudaFuncSetAttribute(attn_mma<1>, cudaFuncAttributeMaxDynamicSharedMemorySize, SMEM_BYTES);
    cudaFuncSetAttribute(attn_mma<0>, cudaFuncAttributeMaxDynamicSharedMemorySize, SMEM_BYTES);

    prep_kernel<<<NN / 64, 256>>>(user, item, W0, b0, a0, 0);
    attn_mma<1><<<(NN / TILE_I) * KSPLIT, TPB, SMEM_BYTES>>>(adj);   // fused: packs adj bits
    prep_kernel<<<NN / 64, 256>>>(nullptr, nullptr, W1, b1, a1, 1);  // fused combine
    attn_mma<0><<<(NN / TILE_I) * KSPLIT, TPB, SMEM_BYTES>>>(adj);   // reads packed bits
    final_kernel<<<NN / 64, 256>>>(ow, ob, (float*)d_out);           // fused combine
}

// round 16
// speedup vs baseline: 1.0902x; 1.0902x over previous
#include <cuda_runtime.h>
#include <cuda_fp16.h>
#include <stdint.h>

#define NN 8192
#define DH 64
#define KC 64              // j's per chunk
#define KSPLIT 2
#define KHALF (NN / KSPLIT)
#define NCH (KHALF / KC)   // 64 chunks
#define TPB 256
#define TILE_I 64
// smem: W tile 64x64 fp16 (8KB) x2, B tile 64x64 fp16 (8KB) x2
#define WOFF0 0
#define WOFF1 8192
#define BOFF0 16384
#define BOFF1 24576
#define SMEM_BYTES 32768

// ---------------- device scratch ----------------
__device__ unsigned short g_adjp[NN * 512];    // packed adjacency bits (8MB)
__device__ unsigned short g_WhT[DH * NN];      // Wh^T fp16 [64][8192]
__device__ uint2 g_iAC[NN];                    // {half2(exp(src)), half2(exp(.2src))}
__device__ unsigned short g_jB[NN];            // half exp(dst)
__device__ unsigned short g_jD[NN];            // half exp(.2 dst)
__device__ float g_part[KSPLIT * NN * DH];     // K-split partial numerators
__device__ float g_den[KSPLIT * NN];           // K-split partial denominators

// ---------------- helpers ----------------
__device__ __forceinline__ uint32_t smem_u32(const void* p) {
    uint32_t a;
    asm("{ .reg .u64 t; cvta.to.shared.u64 t, %1; cvt.u32.u64 %0, t; }" : "=r"(a) : "l"(p));
    return a;
}
#define SWZ(off) ((off) ^ (((off) >> 3) & 0x70))

#define CPA16(d, s) asm volatile("cp.async.cg.shared.global [%0], [%1], 16;" :: "r"(d), "l"(s))
#define CPA_COMMIT() asm volatile("cp.async.commit_group;" ::: "memory")
#define CPA_WAIT0()  asm volatile("cp.async.wait_group 0;" ::: "memory")

__device__ __forceinline__ void ldsm_x4(uint32_t& r0, uint32_t& r1, uint32_t& r2, uint32_t& r3,
                                        uint32_t a) {
    asm volatile("ldmatrix.sync.aligned.m8n8.x4.shared.b16 {%0,%1,%2,%3}, [%4];"
                 : "=r"(r0), "=r"(r1), "=r"(r2), "=r"(r3) : "r"(a));
}
__device__ __forceinline__ void mma16816(float* d, const uint32_t* a, const uint32_t* b) {
    asm volatile("mma.sync.aligned.m16n8k16.row.col.f32.f16.f16.f32 "
                 "{%0,%1,%2,%3}, {%4,%5,%6,%7}, {%8,%9}, {%0,%1,%2,%3};"
                 : "+f"(d[0]), "+f"(d[1]), "+f"(d[2]), "+f"(d[3])
                 : "r"(a[0]), "r"(a[1]), "r"(a[2]), "r"(a[3]), "r"(b[0]), "r"(b[1]));
}

// ---------------- prep: x in smem (broadcast), W row in regs ----------------
__global__ void __launch_bounds__(256) prep_kernel(const float* __restrict__ xa,
                                                   const float* __restrict__ xb,
                                                   const float* __restrict__ Wm,
                                                   const float* __restrict__ bv,
                                                   const float* __restrict__ av, int use_gx) {
    __shared__ float xs[64][64];
    __shared__ float whs[64][65];
    __shared__ float as_[2 * DH];
    __shared__ float bsh[DH];
    __shared__ float inv_s[64];
    int t = threadIdx.x;
    int row0 = blockIdx.x * 64;

    if (t < 2 * DH) as_[t] = av[t];
    if (t < DH) bsh[t] = bv[t];
    if (use_gx && t < 64) {
        int row = row0 + t;
        inv_s[t] = 1.0f / (g_den[row] + g_den[NN + row]);
    }
    __syncthreads();

    {
        int r = t >> 2, q = t & 3;
        int row = row0 + r;
        if (use_gx) {
            const float4* p0 = (const float4*)(g_part + (size_t)row * DH) + q * 4;
            const float4* p1 = (const float4*)(g_part + (size_t)(NN + row) * DH) + q * 4;
            float inv = inv_s[r];
#pragma unroll
            for (int k = 0; k < 4; k++) {
                float4 v0 = p0[k], v1 = p1[k];
                xs[r][q * 16 + 4 * k + 0] = fmaxf((v0.x + v1.x) * inv, 0.f);
                xs[r][q * 16 + 4 * k + 1] = fmaxf((v0.y + v1.y) * inv, 0.f);
                xs[r][q * 16 + 4 * k + 2] = fmaxf((v0.z + v1.z) * inv, 0.f);
                xs[r][q * 16 + 4 * k + 3] = fmaxf((v0.w + v1.w) * inv, 0.f);
            }
        } else {
            const float* xr = row < NN / 2 ? xa + (size_t)row * DH
                                           : xb + (size_t)(row - NN / 2) * DH;
#pragma unroll
            for (int k = 0; k < 4; k++) {
                float4 v = ((const float4*)xr)[q * 4 + k];
                xs[r][q * 16 + 4 * k + 0] = v.x;
                xs[r][q * 16 + 4 * k + 1] = v.y;
                xs[r][q * 16 + 4 * k + 2] = v.z;
                xs[r][q * 16 + 4 * k + 3] = v.w;
            }
        }
    }

    int i = t & 63, g = t >> 6;
    float Wr[64];
#pragma unroll
    for (int k = 0; k < 16; k++) {
        float4 w = ((const float4*)(Wm + (size_t)i * DH))[k];
        Wr[4 * k] = w.x; Wr[4 * k + 1] = w.y; Wr[4 * k + 2] = w.z; Wr[4 * k + 3] = w.w;
    }
    __syncthreads();

    float bias = bsh[i];
    int rbase = g * 16;
#pragma unroll
    for (int r = 0; r < 16; r++) {
        int rr = rbase + r;
        float a0 = 0.f, a1 = 0.f, a2 = 0.f, a3 = 0.f;
#pragma unroll
        for (int k = 0; k < 16; k++) {
            float4 xv = *(const float4*)&xs[rr][4 * k];
            a0 = fmaf(Wr[4 * k + 0], xv.x, a0);
            a1 = fmaf(Wr[4 * k + 1], xv.y, a1);
            a2 = fmaf(Wr[4 * k + 2], xv.z, a2);
            a3 = fmaf(Wr[4 * k + 3], xv.w, a3);
        }
        whs[rr][i] = bias + ((a0 + a1) + (a2 + a3));
    }
    __syncthreads();

    {
        int ii = t >> 2, rq = t & 3;
        uint32_t packed[8];
#pragma unroll
        for (int k = 0; k < 8; k++) {
            __half2 h = __floats2half2_rn(whs[rq * 16 + 2 * k][ii], whs[rq * 16 + 2 * k + 1][ii]);
            packed[k] = *(uint32_t*)&h;
        }
        uint4* dst = (uint4*)(g_WhT + (size_t)ii * NN + row0 + rq * 16);
        dst[0] = make_uint4(packed[0], packed[1], packed[2], packed[3]);
        dst[1] = make_uint4(packed[4], packed[5], packed[6], packed[7]);
    }

    {
        int r = t >> 2, q = t & 3;
        float sv = 0.f, dv = 0.f;
#pragma unroll
        for (int k = 0; k < 16; k++) {
            int ii = q * 16 + k;
            float wh = whs[r][ii];
            sv = fmaf(wh, as_[ii], sv);
            dv = fmaf(wh, as_[DH + ii], dv);
        }
        sv += __shfl_xor_sync(0xffffffffu, sv, 1);
        sv += __shfl_xor_sync(0xffffffffu, sv, 2);
        dv += __shfl_xor_sync(0xffffffffu, dv, 1);
        dv += __shfl_xor_sync(0xffffffffu, dv, 2);
        if (q == 0) {
            int row = row0 + r;
            __half2 Ah = __float2half2_rn(expf(sv));
            __half2 Ch = __float2half2_rn(expf(0.2f * sv));
            g_iAC[row] = make_uint2(*(uint32_t*)&Ah, *(uint32_t*)&Ch);
            g_jB[row] = __half_as_ushort(__float2half_rn(expf(dv)));
            g_jD[row] = __half_as_ushort(__float2half_rn(expf(0.2f * dv)));
        }
    }
}

// ---------------- weight-tile generation (half2) + fp32 row-sum ----------------
// Both layers consume a 16-bit mask word 'bits'; layer 0 builds it from raw adj
// ints first (values are strictly {0,1}) and stores it for layer 1.
template<int L0>
__device__ __forceinline__ void gen_store(char* smemp, uint32_t wo, uint32_t wdst0, uint32_t wdst1,
                                          uint32_t A2, uint32_t C2,
                                          const uint4& B0, const uint4& B1,
                                          const uint4& D0, const uint4& D1,
                                          uint32_t bits_in, const int* vi,
                                          unsigned short* packdst, float& dsum) {
    uint32_t bits = bits_in;
    if (L0) {
        // adj values are 0/1: OR-accumulate 16 bits (1 LOP3 each, fused by ptxas)
        uint32_t pb = 0;
#pragma unroll
        for (int p = 0; p < 16; p++) pb |= ((uint32_t)vi[p] & 1u) << p;
        bits = pb;
        *packdst = (unsigned short)pb;
    }

    uint32_t Bw[8] = {B0.x, B0.y, B0.z, B0.w, B1.x, B1.y, B1.z, B1.w};
    uint32_t Dw[8] = {D0.x, D0.y, D0.z, D0.w, D1.x, D1.y, D1.z, D1.w};
    uint32_t wv[8];
    __half2 A2h = *(__half2*)&A2, C2h = *(__half2*)&C2;
#pragma unroll
    for (int p = 0; p < 8; p++) {
        __half2 ab = __hmul2(A2h, *(__half2*)&Bw[p]);
        __half2 cd = __hmul2(C2h, *(__half2*)&Dw[p]);
        __half2 w = __hmax2(ab, cd);      // exp(leaky_relu(src+dst)) — exp is monotone
        uint32_t e = (bits >> (2 * p)) & 3u;
        uint32_t m = ((e * 0x8001u) & 0x10001u) * 0xFFFFu;
        wv[p] = (*(uint32_t*)&w) & m;
    }
    // fp32 row-sum of the masked fp16 weights (softmax denominator)
    __half2 s01 = __hadd2(*(__half2*)&wv[0], *(__half2*)&wv[1]);
    __half2 s23 = __hadd2(*(__half2*)&wv[2], *(__half2*)&wv[3]);
    __half2 s45 = __hadd2(*(__half2*)&wv[4], *(__half2*)&wv[5]);
    __half2 s67 = __hadd2(*(__half2*)&wv[6], *(__half2*)&wv[7]);
    float2 f0 = __half22float2(__hadd2(s01, s23));
    float2 f1 = __half22float2(__hadd2(s45, s67));
    dsum += (f0.x + f0.y) + (f1.x + f1.y);

    *(uint4*)(smemp + wo + wdst0) = make_uint4(wv[0], wv[1], wv[2], wv[3]);
    *(uint4*)(smemp + wo + wdst1) = make_uint4(wv[4], wv[5], wv[6], wv[7]);
}

// ---------------- attn: HMMA flash-GAT, 64x4096 per CTA (R14 GEMM mapping) ----------------
template<int L0>
__global__ void __launch_bounds__(TPB, 3) attn_mma(const int* __restrict__ adj) {
    extern __shared__ char smem[];
    uint32_t sb = smem_u32(smem);
    int t = threadIdx.x, wid = t >> 5, lane = t & 31;
    int tile = blockIdx.x >> 1, ks = blockIdx.x & 1;
    int i0 = tile * TILE_I, jbase = ks * KHALF;

    // ---- gen mapping: thread -> row i_loc, 16 j's at quarter jq16 ----
    int i_loc = t >> 2, jq16 = t & 3;
    int irow = i0 + i_loc;
    uint2 ac = g_iAC[irow];
    uint32_t wdst0 = SWZ((uint32_t)(i_loc * 128 + jq16 * 32));
    uint32_t wdst1 = SWZ((uint32_t)(i_loc * 128 + jq16 * 32 + 16));
    const uint4* pB = (const uint4*)(g_jB + jbase) + jq16 * 2;
    const uint4* pD = (const uint4*)(g_jD + jbase) + jq16 * 2;
    const int4* pAdj = (const int4*)(adj + (size_t)irow * NN + jbase) + jq16 * 4;
    unsigned short* pPack = g_adjp + (size_t)irow * 512 + (jbase >> 4) + jq16;
    float dsum = 0.f;

    // ---- B staging (cp.async): 512 16B segs = 2/thread ----
    int s0 = t, s1 = t + 256;
    uint32_t bd0 = SWZ((uint32_t)((s0 >> 3) * 128 + (s0 & 7) * 16));
    uint32_t bd1 = SWZ((uint32_t)((s1 >> 3) * 128 + (s1 & 7) * 16));
    const unsigned short* bs0p = g_WhT + (size_t)(s0 >> 3) * NN + jbase + (s0 & 7) * 8;
    const unsigned short* bs1p = g_WhT + (size_t)(s1 >> 3) * NN + jbase + (s1 & 7) * 8;

    // ---- GEMM mapping: 8 warps = 4 M-tiles(16) x 2 N-halves(32) ----
    int wm = wid & 3, wn = wid >> 2;
    int lr = lane & 7, lsel = lane >> 3;
    float acc[4][4];
#pragma unroll
    for (int n = 0; n < 4; n++)
#pragma unroll
        for (int p = 0; p < 4; p++) acc[n][p] = 0.f;

    // ---- prefetch regs for chunk 0 ----
    uint4 Bq0 = pB[0], Bq1 = pB[1], Dq0 = pD[0], Dq1 = pD[1];
    uint32_t bits = 0;
    int4 rv[4];
    if (L0) {
        rv[0] = __ldcs(pAdj + 0); rv[1] = __ldcs(pAdj + 1);
        rv[2] = __ldcs(pAdj + 2); rv[3] = __ldcs(pAdj + 3);
    } else bits = pPack[0];

    // ---- stage chunk 0 ----
    CPA16(sb + BOFF0 + bd0, bs0p);
    CPA16(sb + BOFF0 + bd1, bs1p);
    CPA_COMMIT();
    gen_store<L0>(smem, WOFF0, wdst0, wdst1, ac.x, ac.y, Bq0, Bq1, Dq0, Dq1,
                  bits, (const int*)rv, pPack, dsum);
    Bq0 = pB[8]; Bq1 = pB[9]; Dq0 = pD[8]; Dq1 = pD[9];
    if (L0) {
        rv[0] = __ldcs(pAdj + 16); rv[1] = __ldcs(pAdj + 17);
        rv[2] = __ldcs(pAdj + 18); rv[3] = __ldcs(pAdj + 19);
    } else bits = pPack[4];
    CPA_WAIT0();
    __syncthreads();

    for (int c = 0; c < NCH; c++) {
        int buf = c & 1;
        if (c + 1 < NCH) {
            int nb = buf ^ 1;
            uint32_t bo = nb ? BOFF1 : BOFF0, wo = nb ? WOFF1 : WOFF0;
            CPA16(sb + bo + bd0, bs0p + (c + 1) * 64);
            CPA16(sb + bo + bd1, bs1p + (c + 1) * 64);
            CPA_COMMIT();
            gen_store<L0>(smem, wo, wdst0, wdst1, ac.x, ac.y, Bq0, Bq1, Dq0, Dq1,
                          bits, (const int*)rv, pPack + (c + 1) * 4, dsum);
            if (c + 2 < NCH) {
                Bq0 = pB[(c + 2) * 8]; Bq1 = pB[(c + 2) * 8 + 1];
                Dq0 = pD[(c + 2) * 8]; Dq1 = pD[(c + 2) * 8 + 1];
                if (L0) {
                    rv[0] = __ldcs(pAdj + (c + 2) * 16);     rv[1] = __ldcs(pAdj + (c + 2) * 16 + 1);
                    rv[2] = __ldcs(pAdj + (c + 2) * 16 + 2); rv[3] = __ldcs(pAdj + (c + 2) * 16 + 3);
                } else bits = pPack[(c + 2) * 4];
            }
        }

        // ---- GEMM on chunk c ----
        uint32_t wbase = sb + (buf ? WOFF1 : WOFF0);
        uint32_t bbase = sb + (buf ? BOFF1 : BOFF0);
#pragma unroll
        for (int k = 0; k < 4; k++) {
            uint32_t af[4], bf[8];
            uint32_t a_adr = wbase + SWZ((uint32_t)((wm * 16 + lr + (lsel & 1) * 8) * 128 + ((lsel >> 1) * 8 + k * 16) * 2));
            ldsm_x4(af[0], af[1], af[2], af[3], a_adr);
#pragma unroll
            for (int p = 0; p < 2; p++) {
                uint32_t b_adr = bbase + SWZ((uint32_t)((wn * 32 + p * 16 + lr + (lsel >> 1) * 8) * 128 + ((lsel & 1) * 8 + k * 16) * 2));
                ldsm_x4(bf[p * 4 + 0], bf[p * 4 + 1], bf[p * 4 + 2], bf[p * 4 + 3], b_adr);
            }
            mma16816(acc[0], af, bf + 0);
            mma16816(acc[1], af, bf + 2);
            mma16816(acc[2], af, bf + 4);
            mma16816(acc[3], af, bf + 6);
        }
        CPA_WAIT0();
        __syncthreads();
    }

    // ---- denominator: reduce over the 4 gen threads of each row ----
    dsum += __shfl_xor_sync(0xffffffffu, dsum, 1);
    dsum += __shfl_xor_sync(0xffffffffu, dsum, 2);
    if (jq16 == 0) g_den[(size_t)ks * NN + irow] = dsum;

    // ---- epilogue: write partial numerators ----
    int row0 = i0 + wm * 16 + (lane >> 2);
    float* base = g_part + (size_t)ks * NN * DH;
#pragma unroll
    for (int nt = 0; nt < 4; nt++) {
        int col = wn * 32 + nt * 8 + (lane & 3) * 2;
        *(float2*)(base + (size_t)row0 * DH + col) = make_float2(acc[nt][0], acc[nt][1]);
        *(float2*)(base + (size_t)(row0 + 8) * DH + col) = make_float2(acc[nt][2], acc[nt][3]);
    }
}

// ---------------- final: fused combine + out = x @ out_w^T + out_b ----------------
__global__ void __launch_bounds__(256) final_kernel(const float* __restrict__ Wm,
                                                    const float* __restrict__ bv,
                                                    float* __restrict__ out) {
    __shared__ float xs[64][64];
    __shared__ float bsh[DH];
    __shared__ float inv_s[64];
    int t = threadIdx.x;
    int row0 = blockIdx.x * 64;
    if (t < DH) bsh[t] = bv[t];
    if (t < 64) {
        int row = row0 + t;
        inv_s[t] = 1.0f / (g_den[row] + g_den[NN + row]);
    }
    __syncthreads();

    {
        int r = t >> 2, q = t & 3;
        int row = row0 + r;
        const float4* p0 = (const float4*)(g_part + (size_t)row * DH) + q * 4;
        const float4* p1 = (const float4*)(g_part + (size_t)(NN + row) * DH) + q * 4;
        float inv = inv_s[r];
#pragma unroll
        for (int k = 0; k < 4; k++) {
            float4 v0 = p0[k], v1 = p1[k];
            xs[r][q * 16 + 4 * k + 0] = fmaxf((v0.x + v1.x) * inv, 0.f);
            xs[r][q * 16 + 4 * k + 1] = fmaxf((v0.y + v1.y) * inv, 0.f);
            xs[r][q * 16 + 4 * k + 2] = fmaxf((v0.z + v1.z) * inv, 0.f);
            xs[r][q * 16 + 4 * k + 3] = fmaxf((v0.w + v1.w) * inv, 0.f);
        }
    }

    int i = t & 63, g = t >> 6;
    float Wr[64];
#pragma unroll
    for (int k = 0; k < 16; k++) {
        float4 w = ((const float4*)(Wm + (size_t)i * DH))[k];
        Wr[4 * k] = w.x; Wr[4 * k + 1] = w.y; Wr[4 * k + 2] = w.z; Wr[4 * k + 3] = w.w;
    }
    __syncthreads();

    float bias = bsh[i];
    int rbase = g * 16;
#pragma unroll
    for (int r = 0; r < 16; r++) {
        int rr = rbase + r;
        float a0 = 0.f, a1 = 0.f, a2 = 0.f, a3 = 0.f;
#pragma unroll
        for (int k = 0; k < 16; k++) {
            float4 xv = *(const float4*)&xs[rr][4 * k];
            a0 = fmaf(Wr[4 * k + 0], xv.x, a0);
            a1 = fmaf(Wr[4 * k + 1], xv.y, a1);
            a2 = fmaf(Wr[4 * k + 2], xv.z, a2);
            a3 = fmaf(Wr[4 * k + 3], xv.w, a3);
        }
        out[(size_t)(row0 + rr) * DH + i] = bias + ((a0 + a1) + (a2 + a3));
    }
}

// ---------------- launch ----------------
extern "C" void kernel_launch(void* const* d_in, const int* in_sizes, int n_in,
                              void* d_out, int out_size) {
    const int*   adj  = (const int*)d_in[0];
    const float* user = (const float*)d_in[1];
    const float* item = (const float*)d_in[2];
    const float* W0   = (const float*)d_in[3];
    const float* b0   = (const float*)d_in[4];
    const float* a0   = (const float*)d_in[5];
    const float* W1   = (const float*)d_in[6];
    const float* b1   = (const float*)d_in[7];
    const float* a1   = (const float*)d_in[8];
    const float* ow   = (const float*)d_in[9];
    const float* ob   = (const float*)d_in[10];

    cudaFuncSetAttribute(attn_mma<1>, cudaFuncAttributeMaxDynamicSharedMemorySize, SMEM_BYTES);
    cudaFuncSetAttribute(attn_mma<0>, cudaFuncAttributeMaxDynamicSharedMemorySize, SMEM_BYTES);

    prep_kernel<<<NN / 64, 256>>>(user, item, W0, b0, a0, 0);
    attn_mma<1><<<(NN / TILE_I) * KSPLIT, TPB, SMEM_BYTES>>>(adj);   // fused: packs adj bits
    prep_kernel<<<NN / 64, 256>>>(nullptr, nullptr, W1, b1, a1, 1);  // fused combine
    attn_mma<0><<<(NN / TILE_I) * KSPLIT, TPB, SMEM_BYTES>>>(adj);   // reads packed bits
    final_kernel<<<NN / 64, 256>>>(ow, ob, (float*)d_out);           // fused combine
}